// round 1
// baseline (speedup 1.0000x reference)
#include <cuda_runtime.h>

// Problem constants (fixed by the dataset)
#define DIM     128
#define NCLS    50
#define WPITCH  384          // W row stride: [C, 3*D]
#define PPITCH  64           // padded row pitch for P/Q scratch
#define NMAX    50000

// Scratch: P[n] = h[n]·W1^T + b, Q[n] = h[n]·W2^T   (12.8 MB each)
__device__ float g_P[NMAX * PPITCH];
__device__ float g_Q[NMAX * PPITCH];
__device__ int   g_idx64;   // 1 if src/dst are int64, 0 if int32

// ---------------------------------------------------------------------------
// Detect whether index arrays are int64 (jax x64 on) or int32 (x64 off).
// int64 values are < 50000 => every high 32-bit word is zero.
// ---------------------------------------------------------------------------
__global__ void detect_idx_kernel(const void* src, int E) {
    const unsigned int* a = (const unsigned int*)src;
    int n = E < 256 ? E : 256;
    int all_hi_zero = 1;
    for (int i = 0; i < n; i++) {
        if (a[2 * i + 1] != 0u) { all_hi_zero = 0; break; }
    }
    g_idx64 = all_hi_zero;
}

// ---------------------------------------------------------------------------
// Node kernel: P[n][c] = sum_k h[n][k] * W[c][k]        (+ b[c], half == 0)
//              Q[n][c] = sum_k h[n][k] * W[c][128 + k]  (half == 1)
// Thread-per-node, W half staged in smem, broadcast LDS reads.
// ---------------------------------------------------------------------------
__global__ __launch_bounds__(256)
void node_kernel(const float* __restrict__ h,
                 const float* __restrict__ W,
                 const float* __restrict__ b,
                 int N)
{
    __shared__ float wS[NCLS][DIM];   // 25.6 KB
    const int half = blockIdx.y;      // 0 -> W1/P, 1 -> W2/Q

    for (int i = threadIdx.x; i < NCLS * DIM; i += blockDim.x) {
        int c = i >> 7, k = i & 127;
        wS[c][k] = W[c * WPITCH + half * DIM + k];
    }
    __syncthreads();

    int nid = blockIdx.x * blockDim.x + threadIdx.x;
    if (nid >= N) return;

    float acc[NCLS];
#pragma unroll
    for (int c = 0; c < NCLS; c++)
        acc[c] = (half == 0) ? __ldg(&b[c]) : 0.0f;

    const float4* hr = (const float4*)(h + (size_t)nid * DIM);

    for (int kc = 0; kc < DIM / 4; kc += 4) {
        float4 e0 = hr[kc + 0];
        float4 e1 = hr[kc + 1];
        float4 e2 = hr[kc + 2];
        float4 e3 = hr[kc + 3];
#pragma unroll
        for (int c = 0; c < NCLS; c++) {
            const float4* wr = (const float4*)&wS[c][kc * 4];
            float4 w0 = wr[0], w1 = wr[1], w2 = wr[2], w3 = wr[3];
            float s = acc[c];
            s += e0.x * w0.x; s += e0.y * w0.y; s += e0.z * w0.z; s += e0.w * w0.w;
            s += e1.x * w1.x; s += e1.y * w1.y; s += e1.z * w1.z; s += e1.w * w1.w;
            s += e2.x * w2.x; s += e2.y * w2.y; s += e2.z * w2.z; s += e2.w * w2.w;
            s += e3.x * w3.x; s += e3.y * w3.y; s += e3.z * w3.z; s += e3.w * w3.w;
            acc[c] = s;
        }
    }

    float* drow = (half == 0 ? g_P : g_Q) + (size_t)nid * PPITCH;
#pragma unroll
    for (int j = 0; j < 12; j++) {
        float4 v = make_float4(acc[4 * j + 0], acc[4 * j + 1],
                               acc[4 * j + 2], acc[4 * j + 3]);
        *(float4*)(drow + 4 * j) = v;
    }
    drow[48] = acc[48];
    drow[49] = acc[49];
}

// ---------------------------------------------------------------------------
// Edge kernel: out[e][c] = P[src[e]][c] + Q[dst[e]][c] + sum_k e[e][k]*W3[c][k]
// Thread-per-edge. W3 in smem (broadcast LDS). e row streamed via float4.
// ---------------------------------------------------------------------------
__global__ __launch_bounds__(256)
void edge_kernel(const float* __restrict__ efeat,
                 const void*  __restrict__ src,
                 const void*  __restrict__ dst,
                 const float* __restrict__ W,
                 float* __restrict__ out,
                 int E)
{
    __shared__ float wS[NCLS][DIM];   // W3, 25.6 KB

    for (int i = threadIdx.x; i < NCLS * DIM; i += blockDim.x) {
        int c = i >> 7, k = i & 127;
        wS[c][k] = W[c * WPITCH + 2 * DIM + k];
    }
    __syncthreads();

    int eid = blockIdx.x * blockDim.x + threadIdx.x;
    if (eid >= E) return;

    long long s, d;
    if (g_idx64) {
        s = ((const long long*)src)[eid];
        d = ((const long long*)dst)[eid];
    } else {
        s = ((const int*)src)[eid];
        d = ((const int*)dst)[eid];
    }

    // init acc with gathered P[src] + Q[dst] (b already folded into P)
    float acc[NCLS];
    const float4* pr = (const float4*)(g_P + (size_t)s * PPITCH);
    const float4* qr = (const float4*)(g_Q + (size_t)d * PPITCH);
#pragma unroll
    for (int j = 0; j < 12; j++) {
        float4 a = pr[j];
        float4 q = qr[j];
        acc[4 * j + 0] = a.x + q.x;
        acc[4 * j + 1] = a.y + q.y;
        acc[4 * j + 2] = a.z + q.z;
        acc[4 * j + 3] = a.w + q.w;
    }
    acc[48] = g_P[(size_t)s * PPITCH + 48] + g_Q[(size_t)d * PPITCH + 48];
    acc[49] = g_P[(size_t)s * PPITCH + 49] + g_Q[(size_t)d * PPITCH + 49];

    const float4* er = (const float4*)(efeat + (size_t)eid * DIM);

    for (int kc = 0; kc < DIM / 4; kc += 4) {
        float4 e0 = er[kc + 0];
        float4 e1 = er[kc + 1];
        float4 e2 = er[kc + 2];
        float4 e3 = er[kc + 3];
#pragma unroll
        for (int c = 0; c < NCLS; c++) {
            const float4* wr = (const float4*)&wS[c][kc * 4];
            float4 w0 = wr[0], w1 = wr[1], w2 = wr[2], w3 = wr[3];
            float sm = acc[c];
            sm += e0.x * w0.x; sm += e0.y * w0.y; sm += e0.z * w0.z; sm += e0.w * w0.w;
            sm += e1.x * w1.x; sm += e1.y * w1.y; sm += e1.z * w1.z; sm += e1.w * w1.w;
            sm += e2.x * w2.x; sm += e2.y * w2.y; sm += e2.z * w2.z; sm += e2.w * w2.w;
            sm += e3.x * w3.x; sm += e3.y * w3.y; sm += e3.z * w3.z; sm += e3.w * w3.w;
            acc[c] = sm;
        }
    }

    // store 50 floats; row base is 8-byte aligned (eid*200)
    float* orow = out + (size_t)eid * NCLS;
#pragma unroll
    for (int c = 0; c < NCLS; c += 2) {
        float2 v = make_float2(acc[c], acc[c + 1]);
        *(float2*)(orow + c) = v;
    }
}

// ---------------------------------------------------------------------------
extern "C" void kernel_launch(void* const* d_in, const int* in_sizes, int n_in,
                              void* d_out, int out_size)
{
    const float* h  = (const float*)d_in[0];
    const float* e  = (const float*)d_in[1];
    const void*  src = d_in[2];
    const void*  dst = d_in[3];
    const float* W  = (const float*)d_in[4];
    const float* b  = (const float*)d_in[5];

    int N = in_sizes[0] / DIM;   // 50000
    int E = in_sizes[1] / DIM;   // 500000
    if (N > NMAX) N = NMAX;

    detect_idx_kernel<<<1, 1>>>(src, E);

    dim3 ngrid((N + 255) / 256, 2);
    node_kernel<<<ngrid, 256>>>(h, W, b, N);

    edge_kernel<<<(E + 255) / 256, 256>>>(e, src, dst, W, (float*)d_out, E);
}

// round 2
// speedup vs baseline: 1.0336x; 1.0336x over previous
#include <cuda_runtime.h>

#define DIM     128
#define NCLS    50
#define PAIRS   25           // NCLS/2 class pairs
#define WPITCH  384          // W row stride: [C, 3*D]
#define PPITCH  64           // padded row pitch for P/Q scratch (floats)
#define NMAX    50000
#define WROW    26           // smem pairs per k row (25 + 1 pad, 208B, 16B-aligned)

typedef unsigned long long ull;

__device__ float g_P[NMAX * PPITCH];
__device__ float g_Q[NMAX * PPITCH];
__device__ int   g_idx64;

// ---- packed f32x2 helpers ---------------------------------------------------
__device__ __forceinline__ ull fma2(ull a, ull b, ull c) {
    ull d;
    asm("fma.rn.f32x2 %0, %1, %2, %3;" : "=l"(d) : "l"(a), "l"(b), "l"(c));
    return d;
}
__device__ __forceinline__ ull add2(ull a, ull b) {
    ull d;
    asm("add.rn.f32x2 %0, %1, %2;" : "=l"(d) : "l"(a), "l"(b));
    return d;
}
__device__ __forceinline__ ull dup2(float x) {
    ull d; unsigned int u = __float_as_uint(x);
    asm("mov.b64 %0, {%1, %1};" : "=l"(d) : "r"(u));
    return d;
}

// ---------------------------------------------------------------------------
__global__ void detect_idx_kernel(const void* src, int E) {
    const unsigned int* a = (const unsigned int*)src;
    int n = E < 256 ? E : 256;
    int all_hi_zero = 1;
    for (int i = 0; i < n; i++)
        if (a[2 * i + 1] != 0u) { all_hi_zero = 0; break; }
    g_idx64 = all_hi_zero;
}

// ---------------------------------------------------------------------------
// Node kernel: P[n] = h[n]·W1^T + b (half 0),  Q[n] = h[n]·W2^T (half 1).
// Packed class pairs, FFMA2.
// ---------------------------------------------------------------------------
__global__ __launch_bounds__(256)
void node_kernel(const float* __restrict__ h,
                 const float* __restrict__ W,
                 const float* __restrict__ b,
                 int N)
{
    __shared__ float2 wp[DIM * WROW];   // 26.6 KB, packed {W[2c][k], W[2c+1][k]}
    const int half = blockIdx.y;
    const int off  = half * DIM;

    for (int i = threadIdx.x; i < DIM * PAIRS; i += blockDim.x) {
        int k = i / PAIRS, c = i % PAIRS;
        wp[k * WROW + c] = make_float2(W[(2 * c) * WPITCH + off + k],
                                       W[(2 * c + 1) * WPITCH + off + k]);
    }
    __syncthreads();

    int nid = blockIdx.x * blockDim.x + threadIdx.x;
    if (nid >= N) return;

    ull acc[PAIRS];
    if (half == 0) {
        const ull* b2 = (const ull*)b;
#pragma unroll
        for (int c = 0; c < PAIRS; c++) acc[c] = b2[c];
    } else {
#pragma unroll
        for (int c = 0; c < PAIRS; c++) acc[c] = 0ull;
    }

    const float4* hr = (const float4*)(h + (size_t)nid * DIM);

#pragma unroll 1
    for (int kc = 0; kc < DIM / 4; kc++) {
        float4 f = hr[kc];
        float fs[4] = {f.x, f.y, f.z, f.w};
#pragma unroll
        for (int kk = 0; kk < 4; kk++) {
            int k = kc * 4 + kk;
            ull a = dup2(fs[kk]);
            const ulonglong2* wrow = (const ulonglong2*)&wp[k * WROW];
#pragma unroll
            for (int j = 0; j < 12; j++) {
                ulonglong2 w = wrow[j];
                acc[2 * j]     = fma2(a, w.x, acc[2 * j]);
                acc[2 * j + 1] = fma2(a, w.y, acc[2 * j + 1]);
            }
            ull w24 = ((const ull*)wrow)[24];
            acc[24] = fma2(a, w24, acc[24]);
        }
    }

    ull* drow = (ull*)((half == 0 ? g_P : g_Q) + (size_t)nid * PPITCH);
#pragma unroll
    for (int c = 0; c < PAIRS; c++) drow[c] = acc[c];
}

// ---------------------------------------------------------------------------
// Edge kernel: 2 edges per thread, shared W3 LDS, FFMA2 packed class pairs.
// out[e][c] = P[src[e]][c] + Q[dst[e]][c] + e_row · W3[c]^T
// ---------------------------------------------------------------------------
__global__ __launch_bounds__(128)
void edge_kernel(const float* __restrict__ efeat,
                 const void*  __restrict__ src,
                 const void*  __restrict__ dst,
                 const float* __restrict__ W,
                 float* __restrict__ out,
                 int E)
{
    __shared__ float2 wp[DIM * WROW];   // packed W3

    for (int i = threadIdx.x; i < DIM * PAIRS; i += blockDim.x) {
        int k = i / PAIRS, c = i % PAIRS;
        wp[k * WROW + c] = make_float2(W[(2 * c) * WPITCH + 2 * DIM + k],
                                       W[(2 * c + 1) * WPITCH + 2 * DIM + k]);
    }
    __syncthreads();

    long long t = (long long)blockIdx.x * blockDim.x + threadIdx.x;
    long long e0 = 2 * t;
    if (e0 >= E) return;
    long long e1 = e0 + 1;
    const bool has1 = (e1 < E);
    const long long e1c = has1 ? e1 : e0;

    long long s0, d0, s1, d1;
    if (g_idx64) {
        const long long* S = (const long long*)src;
        const long long* Dd = (const long long*)dst;
        s0 = S[e0]; d0 = Dd[e0]; s1 = S[e1c]; d1 = Dd[e1c];
    } else {
        const int* S = (const int*)src;
        const int* Dd = (const int*)dst;
        s0 = S[e0]; d0 = Dd[e0]; s1 = S[e1c]; d1 = Dd[e1c];
    }

    ull accA[PAIRS], accB[PAIRS];
    {
        const ull* p0 = (const ull*)(g_P + (size_t)s0 * PPITCH);
        const ull* q0 = (const ull*)(g_Q + (size_t)d0 * PPITCH);
        const ull* p1 = (const ull*)(g_P + (size_t)s1 * PPITCH);
        const ull* q1 = (const ull*)(g_Q + (size_t)d1 * PPITCH);
#pragma unroll
        for (int c = 0; c < PAIRS; c++) {
            accA[c] = add2(p0[c], q0[c]);
            accB[c] = add2(p1[c], q1[c]);
        }
    }

    const float4* er0 = (const float4*)(efeat + (size_t)e0 * DIM);
    const float4* er1 = (const float4*)(efeat + (size_t)e1c * DIM);

#pragma unroll 1
    for (int kc = 0; kc < DIM / 4; kc++) {
        float4 f0 = er0[kc];
        float4 f1 = er1[kc];
        float fs0[4] = {f0.x, f0.y, f0.z, f0.w};
        float fs1[4] = {f1.x, f1.y, f1.z, f1.w};
#pragma unroll
        for (int kk = 0; kk < 4; kk++) {
            int k = kc * 4 + kk;
            ull a0 = dup2(fs0[kk]);
            ull a1 = dup2(fs1[kk]);
            const ulonglong2* wrow = (const ulonglong2*)&wp[k * WROW];
#pragma unroll
            for (int j = 0; j < 12; j++) {
                ulonglong2 w = wrow[j];
                accA[2 * j]     = fma2(a0, w.x, accA[2 * j]);
                accA[2 * j + 1] = fma2(a0, w.y, accA[2 * j + 1]);
                accB[2 * j]     = fma2(a1, w.x, accB[2 * j]);
                accB[2 * j + 1] = fma2(a1, w.y, accB[2 * j + 1]);
            }
            ull w24 = ((const ull*)wrow)[24];
            accA[24] = fma2(a0, w24, accA[24]);
            accB[24] = fma2(a1, w24, accB[24]);
        }
    }

    ull* o0 = (ull*)(out + (size_t)e0 * NCLS);
#pragma unroll
    for (int c = 0; c < PAIRS; c++) o0[c] = accA[c];

    if (has1) {
        ull* o1 = (ull*)(out + (size_t)e1 * NCLS);
#pragma unroll
        for (int c = 0; c < PAIRS; c++) o1[c] = accB[c];
    }
}

// ---------------------------------------------------------------------------
extern "C" void kernel_launch(void* const* d_in, const int* in_sizes, int n_in,
                              void* d_out, int out_size)
{
    const float* h   = (const float*)d_in[0];
    const float* e   = (const float*)d_in[1];
    const void*  src = d_in[2];
    const void*  dst = d_in[3];
    const float* W   = (const float*)d_in[4];
    const float* b   = (const float*)d_in[5];

    int N = in_sizes[0] / DIM;   // 50000
    int E = in_sizes[1] / DIM;   // 500000
    if (N > NMAX) N = NMAX;

    detect_idx_kernel<<<1, 1>>>(src, E);

    dim3 ngrid((N + 255) / 256, 2);
    node_kernel<<<ngrid, 256>>>(h, W, b, N);

    int nthreads = (E + 1) / 2;
    edge_kernel<<<(nthreads + 127) / 128, 128>>>(e, src, dst, W, (float*)d_out, E);
}